// round 7
// baseline (speedup 1.0000x reference)
#include <cuda_runtime.h>
#include <cuda_fp16.h>
#include <cstdint>
#include <cstddef>

// out[M,N] = x[M,K] @ (w[K,N] + 2 * lora_a[K,16] @ lora_b[16,F])
#define M_DIM 8192
#define N_DIM 8192
#define K_DIM 2048
#define SCALE 2.0f

// Scratch (device globals — allocation-free per harness rules).
// g_xh: x -> fp16 (rn), k-permuted within 16-groups, [M,K]
// g_wh: fused W' = w + 2*A@B -> fp16, TRANSPOSED [N,K], k-permuted
__device__ __align__(16) __half g_xh[(size_t)M_DIM * K_DIM];
__device__ __align__(16) __half g_wh[(size_t)N_DIM * K_DIM];

// k-permutation Q within each 16-group:
// logical {2t,2t+1,2t+8,2t+9} -> phys {4t..4t+3}  (t = 0..3)
// Applied to BOTH operands, so dot products (and the GEMM) are unchanged.
// Makes every m16n8k16 fragment k-quad physically contiguous (one LDS.64).

// ---------------------------------------------------------------------------
// Kernel 1: x -> fp16 + Q-permute. One thread = one 16-group.
// ---------------------------------------------------------------------------
__global__ __launch_bounds__(256) void prep_x(const float4* __restrict__ x,
                                              uint4* __restrict__ xh) {
    const size_t i = (size_t)blockIdx.x * 256 + threadIdx.x;  // 16-group index
    const float4 v0 = x[i * 4 + 0];   // l0..3
    const float4 v1 = x[i * 4 + 1];   // l4..7
    const float4 v2 = x[i * 4 + 2];   // l8..11
    const float4 v3 = x[i * 4 + 3];   // l12..15
    __half2 h[8];
    h[0] = __floats2half2_rn(v0.x, v0.y);  // l0,l1
    h[1] = __floats2half2_rn(v2.x, v2.y);  // l8,l9
    h[2] = __floats2half2_rn(v0.z, v0.w);  // l2,l3
    h[3] = __floats2half2_rn(v2.z, v2.w);  // l10,l11
    h[4] = __floats2half2_rn(v1.x, v1.y);  // l4,l5
    h[5] = __floats2half2_rn(v3.x, v3.y);  // l12,l13
    h[6] = __floats2half2_rn(v1.z, v1.w);  // l6,l7
    h[7] = __floats2half2_rn(v3.z, v3.w);  // l14,l15
    const uint4* u = reinterpret_cast<const uint4*>(h);
    xh[i * 2 + 0] = u[0];
    xh[i * 2 + 1] = u[1];
}

// ---------------------------------------------------------------------------
// Kernel 2: g_wh[n][Q(k)] = fp16(w[k][n] + 2*(A@B)[k][n]); 32x32 transpose
// ---------------------------------------------------------------------------
__global__ __launch_bounds__(256) void fuse_w_t(const float* __restrict__ w,
                                                const float* __restrict__ la,
                                                const float* __restrict__ lb) {
    __shared__ float t[32][33];
    __shared__ float bs[16][32];
    const int n0 = blockIdx.x * 32, k0 = blockIdx.y * 32;
    const int tid = threadIdx.x;
    const int tx = tid & 31, ty = tid >> 5;
    {
        int i0 = tid;
        bs[i0 >> 5][i0 & 31] = lb[(size_t)(i0 >> 5) * N_DIM + n0 + (i0 & 31)];
        int i1 = tid + 256;
        bs[i1 >> 5][i1 & 31] = lb[(size_t)(i1 >> 5) * N_DIM + n0 + (i1 & 31)];
    }
    __syncthreads();
#pragma unroll
    for (int i = 0; i < 4; i++) {
        const int kl = ty + 8 * i;
        const int k = k0 + kl;
        const float* ar = la + (size_t)k * 16;
        float acc = 0.f;
#pragma unroll
        for (int r = 0; r < 16; r++) acc += ar[r] * bs[r][tx];
        t[kl][tx] = w[(size_t)k * N_DIM + n0 + tx] + SCALE * acc;
    }
    __syncthreads();
    // Q(k) within 16-group: 4*((k>>1)&3) + (k&1) + 2*((k>>3)&1)
    const int wi = tx & 15;
    const int qk = (tx & 16) + 4 * ((wi >> 1) & 3) + (wi & 1) + 2 * ((wi >> 3) & 1);
#pragma unroll
    for (int i = 0; i < 4; i++) {
        const int nl = ty + 8 * i;
        g_wh[(size_t)(n0 + nl) * K_DIM + k0 + qk] = __float2half_rn(t[tx][nl]);
    }
}

// ---------------------------------------------------------------------------
// Kernel 3: fp16 mma.sync GEMM (f32 accum). CTA 128x256 / 256 threads,
//           warp tile 64x64 (2M x 4N), KTILE 64, 3-stage cp.async pipeline
//           with wait_group(1) — barrier never waits on memory.
// ---------------------------------------------------------------------------
constexpr int KTILE = 64;                    // halves per k-tile
constexpr int STRIDE = 80;                   // 64 + 16 pad (halves)
constexpr int A_ST = 128 * STRIDE;           // 10240 halves (20 KB)
constexpr int B_ST = 256 * STRIDE;           // 20480 halves (40 KB)
constexpr int STAGE = A_ST + B_ST;           // 30720 halves (60 KB)
constexpr int STAGES = 3;
constexpr int SMEM_BYTES = STAGES * STAGE * 2;  // 184320 B

__device__ __forceinline__ void lds64(uint32_t& a, uint32_t& b, uint32_t addr) {
    asm volatile("ld.shared.v2.b32 {%0,%1}, [%2];" : "=r"(a), "=r"(b) : "r"(addr));
}
__device__ __forceinline__ void mma16(float c[4], const uint32_t a[4], const uint32_t b[2]) {
    asm volatile(
        "mma.sync.aligned.m16n8k16.row.col.f32.f16.f16.f32 "
        "{%0,%1,%2,%3}, {%4,%5,%6,%7}, {%8,%9}, {%0,%1,%2,%3};\n"
        : "+f"(c[0]), "+f"(c[1]), "+f"(c[2]), "+f"(c[3])
        : "r"(a[0]), "r"(a[1]), "r"(a[2]), "r"(a[3]), "r"(b[0]), "r"(b[1]));
}

__global__ __launch_bounds__(256, 1) void gemm_f16(const __half* __restrict__ A,
                                                   const __half* __restrict__ B,
                                                   float* __restrict__ C) {
    extern __shared__ __half smem[];
    const int tid = threadIdx.x;
    const int lane = tid & 31;
    const int warp = tid >> 5;   // 0..7
    const int wm = warp >> 2;    // 2 warps along M (64 rows)
    const int wn = warp & 3;     // 4 warps along N (64 cols)
    const int grp = lane >> 2;   // 0..7
    const int tig = lane & 3;    // 0..3
    const int blockM = blockIdx.y * 128;
    const int blockN = blockIdx.x * 256;

    const uint32_t smem_u = (uint32_t)__cvta_generic_to_shared(smem);

    float acc[4][8][4];
#pragma unroll
    for (int i = 0; i < 4; i++)
#pragma unroll
        for (int j = 0; j < 8; j++)
#pragma unroll
            for (int l = 0; l < 4; l++) acc[i][j][l] = 0.f;

    // A tile: 128 rows x 8 chunks (16B) = 1024 -> 4/thread
    // B tile: 256 rows x 8 chunks       = 2048 -> 8/thread
    auto load_stage = [&](int s, int k0) {
        const uint32_t baseA = smem_u + (uint32_t)(s * STAGE) * 2u;
        const uint32_t baseB = baseA + (uint32_t)A_ST * 2u;
#pragma unroll
        for (int i = 0; i < 4; i++) {
            const int idx = tid + i * 256;
            const int row = idx >> 3, ch = idx & 7;
            const __half* g = A + (size_t)(blockM + row) * K_DIM + k0 + ch * 8;
            const uint32_t d = baseA + (uint32_t)(row * STRIDE + ch * 8) * 2u;
            asm volatile("cp.async.cg.shared.global [%0], [%1], 16;\n" ::"r"(d), "l"(g));
        }
#pragma unroll
        for (int i = 0; i < 8; i++) {
            const int idx = tid + i * 256;
            const int row = idx >> 3, ch = idx & 7;
            const __half* g = B + (size_t)(blockN + row) * K_DIM + k0 + ch * 8;
            const uint32_t d = baseB + (uint32_t)(row * STRIDE + ch * 8) * 2u;
            asm volatile("cp.async.cg.shared.global [%0], [%1], 16;\n" ::"r"(d), "l"(g));
        }
    };

    load_stage(0, 0);
    asm volatile("cp.async.commit_group;\n" ::: "memory");
    load_stage(1, KTILE);
    asm volatile("cp.async.commit_group;\n" ::: "memory");

    const int KTILES = K_DIM / KTILE;  // 32
    int st = 0;
    for (int kt = 0; kt < KTILES; kt++) {
        asm volatile("cp.async.wait_group 1;\n" ::: "memory");
        __syncthreads();

        // prefetch kt+2 into the stage consumed at kt-1 (safe: all warps
        // passed the kt barrier, hence finished kt-1's compute)
        if (kt + 2 < KTILES) {
            int ps = st + 2; if (ps >= STAGES) ps -= STAGES;
            load_stage(ps, (kt + 2) * KTILE);
        }
        asm volatile("cp.async.commit_group;\n" ::: "memory");

        const uint32_t aTh = smem_u +
            (uint32_t)(st * STAGE + (wm * 64 + grp) * STRIDE + 4 * tig) * 2u;
        const uint32_t bTh = smem_u +
            (uint32_t)(st * STAGE + A_ST + (wn * 64 + grp) * STRIDE + 4 * tig) * 2u;
#pragma unroll
        for (int ks = 0; ks < 4; ks++) {          // 4 x k16 per KTILE=64
            const uint32_t ko = (uint32_t)(ks * 16) * 2u;
            uint32_t af[4][4], bf[8][2];
#pragma unroll
            for (int mi = 0; mi < 4; mi++) {
                const uint32_t ap = aTh + (uint32_t)(mi * 16 * STRIDE) * 2u + ko;
                lds64(af[mi][0], af[mi][2], ap);                               // row grp
                lds64(af[mi][1], af[mi][3], ap + (uint32_t)(8 * STRIDE) * 2u); // row grp+8
            }
#pragma unroll
            for (int ni = 0; ni < 8; ni++) {
                const uint32_t bp = bTh + (uint32_t)(ni * 8 * STRIDE) * 2u + ko;
                lds64(bf[ni][0], bf[ni][1], bp);
            }
#pragma unroll
            for (int mi = 0; mi < 4; mi++)
#pragma unroll
                for (int ni = 0; ni < 8; ni++)
                    mma16(acc[mi][ni], af[mi], bf[ni]);
        }
        if (++st == STAGES) st = 0;
    }

    // Epilogue: c0/c1 at (row, 2*tig[+1]); c2/c3 at (row+8, ...)
#pragma unroll
    for (int mi = 0; mi < 4; mi++) {
        const int r0 = blockM + wm * 64 + mi * 16 + grp;
#pragma unroll
        for (int ni = 0; ni < 8; ni++) {
            const int c0 = blockN + wn * 64 + ni * 8 + 2 * tig;
            float2 v0 = make_float2(acc[mi][ni][0], acc[mi][ni][1]);
            float2 v1 = make_float2(acc[mi][ni][2], acc[mi][ni][3]);
            *reinterpret_cast<float2*>(C + (size_t)r0 * N_DIM + c0) = v0;
            *reinterpret_cast<float2*>(C + (size_t)(r0 + 8) * N_DIM + c0) = v1;
        }
    }
}

// ---------------------------------------------------------------------------
extern "C" void kernel_launch(void* const* d_in, const int* in_sizes, int n_in,
                              void* d_out, int out_size) {
    const float* x  = (const float*)d_in[0];  // [8192,2048]
    const float* w  = (const float*)d_in[1];  // [2048,8192]
    const float* la = (const float*)d_in[2];  // [2048,16]
    const float* lb = (const float*)d_in[3];  // [16,8192]
    float* out = (float*)d_out;               // [8192,8192]

    void *xh_p = nullptr, *wh_p = nullptr;
    cudaGetSymbolAddress(&xh_p, g_xh);
    cudaGetSymbolAddress(&wh_p, g_wh);

    prep_x<<<(int)(((size_t)M_DIM * K_DIM / 16) / 256), 256>>>(
        (const float4*)x, (uint4*)xh_p);
    fuse_w_t<<<dim3(N_DIM / 32, K_DIM / 32), 256>>>(w, la, lb);

    cudaFuncSetAttribute(gemm_f16, cudaFuncAttributeMaxDynamicSharedMemorySize, SMEM_BYTES);
    gemm_f16<<<dim3(N_DIM / 256, M_DIM / 128), 256, SMEM_BYTES>>>(
        (const __half*)xh_p, (const __half*)wh_p, out);
}

// round 8
// speedup vs baseline: 1.0444x; 1.0444x over previous
#include <cuda_runtime.h>
#include <cuda_fp16.h>
#include <cstdint>
#include <cstddef>

// out[M,N] = x[M,K] @ (w[K,N] + 2 * lora_a[K,16] @ lora_b[16,N])
#define M_DIM 8192
#define N_DIM 8192
#define K_DIM 2048
#define SCALE 2.0f

// Scratch (device globals — allocation-free per harness rules).
// g_xh: x -> fp16 (rn), plain [M,K] row-major
// g_wh: fused W' = w + 2*A@B -> fp16, TRANSPOSED [N,K] (K-contiguous)
__device__ __align__(16) __half g_xh[(size_t)M_DIM * K_DIM];
__device__ __align__(16) __half g_wh[(size_t)N_DIM * K_DIM];

// ---------------------------------------------------------------------------
// Kernel 1 (fused prep): blocks [0, PX_BLOCKS) convert x -> fp16;
// remaining blocks compute W'^T tile-transposed. Runs concurrently on-chip.
// ---------------------------------------------------------------------------
constexpr int PX_BLOCKS = (int)((size_t)M_DIM * K_DIM / 8 / 256);  // 8192
constexpr int FW_BLOCKS_X = N_DIM / 32;  // 256
constexpr int FW_BLOCKS_Y = K_DIM / 32;  // 64

__global__ __launch_bounds__(256) void prep_all(const float4* __restrict__ x,
                                                uint4* __restrict__ xh,
                                                const float* __restrict__ w,
                                                const float* __restrict__ la,
                                                const float* __restrict__ lb,
                                                __half* __restrict__ wh) {
    __shared__ float t[32][33];
    __shared__ float bs[16][32];
    const int bid = blockIdx.x;
    const int tid = threadIdx.x;

    if (bid < PX_BLOCKS) {
        // x -> fp16, straight layout. One thread: 8 floats -> 8 halves.
        const size_t i = (size_t)bid * 256 + tid;
        const float4 v0 = x[i * 2 + 0];
        const float4 v1 = x[i * 2 + 1];
        __half2 h[4];
        h[0] = __floats2half2_rn(v0.x, v0.y);
        h[1] = __floats2half2_rn(v0.z, v0.w);
        h[2] = __floats2half2_rn(v1.x, v1.y);
        h[3] = __floats2half2_rn(v1.z, v1.w);
        xh[i] = *reinterpret_cast<const uint4*>(h);
        return;
    }

    const int b2 = bid - PX_BLOCKS;
    const int n0 = (b2 % FW_BLOCKS_X) * 32;
    const int k0 = (b2 / FW_BLOCKS_X) * 32;
    const int tx = tid & 31, ty = tid >> 5;
    {
        int i0 = tid;
        bs[i0 >> 5][i0 & 31] = lb[(size_t)(i0 >> 5) * N_DIM + n0 + (i0 & 31)];
        int i1 = tid + 256;
        bs[i1 >> 5][i1 & 31] = lb[(size_t)(i1 >> 5) * N_DIM + n0 + (i1 & 31)];
    }
    __syncthreads();
#pragma unroll
    for (int i = 0; i < 4; i++) {
        const int kl = ty + 8 * i;
        const int k = k0 + kl;
        const float* ar = la + (size_t)k * 16;
        float acc = 0.f;
#pragma unroll
        for (int r = 0; r < 16; r++) acc += ar[r] * bs[r][tx];
        t[kl][tx] = w[(size_t)k * N_DIM + n0 + tx] + SCALE * acc;
    }
    __syncthreads();
#pragma unroll
    for (int i = 0; i < 4; i++) {
        const int nl = ty + 8 * i;
        wh[(size_t)(n0 + nl) * K_DIM + k0 + tx] = __float2half_rn(t[tx][nl]);
    }
}

// ---------------------------------------------------------------------------
// Kernel 2: fp16 mma.sync GEMM (f32 accum). CTA 128x128 / 128 threads
// (2 CTAs/SM), warp tile 64x64, KTILE 64, 2-stage cp.async, fragments via
// ldmatrix.m8n8.x4 (8 LDSM per ks instead of 16 LDS.64).
// ---------------------------------------------------------------------------
constexpr int KTILE = 64;                   // halves per k-tile
constexpr int STRIDE = 72;                  // 64 + 8 pad (halves) = 144 B rows
constexpr int T_ST = 128 * STRIDE;          // 9216 halves (18 KB)
constexpr int STAGE = 2 * T_ST;             // A + B per stage (36 KB)
constexpr int SMEM_BYTES = 2 * STAGE * 2;   // 147456 B

__device__ __forceinline__ void ldsm4(uint32_t& r0, uint32_t& r1, uint32_t& r2,
                                      uint32_t& r3, uint32_t addr) {
    asm volatile("ldmatrix.sync.aligned.m8n8.x4.shared.b16 {%0,%1,%2,%3}, [%4];"
                 : "=r"(r0), "=r"(r1), "=r"(r2), "=r"(r3) : "r"(addr));
}
__device__ __forceinline__ void mma16(float c[4], const uint32_t a[4], const uint32_t b[2]) {
    asm volatile(
        "mma.sync.aligned.m16n8k16.row.col.f32.f16.f16.f32 "
        "{%0,%1,%2,%3}, {%4,%5,%6,%7}, {%8,%9}, {%0,%1,%2,%3};\n"
        : "+f"(c[0]), "+f"(c[1]), "+f"(c[2]), "+f"(c[3])
        : "r"(a[0]), "r"(a[1]), "r"(a[2]), "r"(a[3]), "r"(b[0]), "r"(b[1]));
}

__global__ __launch_bounds__(128, 2) void gemm_f16(const __half* __restrict__ A,
                                                   const __half* __restrict__ B,
                                                   float* __restrict__ C) {
    extern __shared__ __half smem[];
    const int tid = threadIdx.x;
    const int lane = tid & 31;
    const int warp = tid >> 5;   // 0..3
    const int wm = warp >> 1;    // 2 warps along M (64 rows)
    const int wn = warp & 1;     // 2 warps along N (64 cols)
    const int grp = lane >> 2;   // 0..7
    const int tig = lane & 3;    // 0..3
    const int blockM = blockIdx.y * 128;
    const int blockN = blockIdx.x * 128;

    const uint32_t smem_u = (uint32_t)__cvta_generic_to_shared(smem);

    float acc[4][8][4];
#pragma unroll
    for (int i = 0; i < 4; i++)
#pragma unroll
        for (int j = 0; j < 8; j++)
#pragma unroll
            for (int l = 0; l < 4; l++) acc[i][j][l] = 0.f;

    // cp.async: each tile = 128 rows x 8 chunks of 16B (KTILE=64 halves)
    auto load_stage = [&](int s, int k0) {
        const uint32_t baseA = smem_u + (uint32_t)(s * STAGE) * 2u;
        const uint32_t baseB = baseA + (uint32_t)T_ST * 2u;
#pragma unroll
        for (int i = 0; i < 8; i++) {
            const int idx = tid + i * 128;
            const int row = idx >> 3, ch = idx & 7;
            const __half* g = A + (size_t)(blockM + row) * K_DIM + k0 + ch * 8;
            const uint32_t d = baseA + (uint32_t)(row * STRIDE + ch * 8) * 2u;
            asm volatile("cp.async.cg.shared.global [%0], [%1], 16;\n" ::"r"(d), "l"(g));
        }
#pragma unroll
        for (int i = 0; i < 8; i++) {
            const int idx = tid + i * 128;
            const int row = idx >> 3, ch = idx & 7;
            const __half* g = B + (size_t)(blockN + row) * K_DIM + k0 + ch * 8;
            const uint32_t d = baseB + (uint32_t)(row * STRIDE + ch * 8) * 2u;
            asm volatile("cp.async.cg.shared.global [%0], [%1], 16;\n" ::"r"(d), "l"(g));
        }
    };

    load_stage(0, 0);
    asm volatile("cp.async.commit_group;\n" ::: "memory");

    // ldmatrix per-thread row/chunk offsets (halves):
    // A x4 (per mi): M0 rows +0..7 k0-7 | M1 rows +8 k0-7 | M2 +0..7 k8-15 | M3 +8 k8-15
    const int aRow = wm * 64 + (lane & 7) + 8 * ((lane >> 3) & 1);
    const int aKc = (lane >> 4) & 1;                 // 0/1 -> k-chunk of 8
    // B x4 (per nj=pair of ni): M0 n(2j)+r k0-7 | M1 n(2j)+r k8-15 | M2 n(2j+1) k0-7 | M3 ... k8-15
    const int bRow = wn * 64 + (lane & 7) + 8 * ((lane >> 4) & 1);
    const int bKc = (lane >> 3) & 1;

    const int KTILES = K_DIM / KTILE;  // 32
    for (int kt = 0; kt < KTILES; kt++) {
        asm volatile("cp.async.wait_group 0;\n" ::: "memory");
        __syncthreads();
        if (kt + 1 < KTILES) load_stage((kt + 1) & 1, (kt + 1) * KTILE);
        asm volatile("cp.async.commit_group;\n" ::: "memory");

        const uint32_t stBase = smem_u + (uint32_t)((kt & 1) * STAGE) * 2u;
        const uint32_t aTh = stBase + (uint32_t)(aRow * STRIDE + aKc * 8) * 2u;
        const uint32_t bTh = stBase + (uint32_t)(T_ST + bRow * STRIDE + bKc * 8) * 2u;
#pragma unroll
        for (int ks = 0; ks < 4; ks++) {          // 4 x k16 per KTILE=64
            const uint32_t ko = (uint32_t)(ks * 16) * 2u;
            uint32_t af[4][4], bf[8][2];
#pragma unroll
            for (int mi = 0; mi < 4; mi++)
                ldsm4(af[mi][0], af[mi][1], af[mi][2], af[mi][3],
                      aTh + (uint32_t)(mi * 16 * STRIDE) * 2u + ko);
#pragma unroll
            for (int nj = 0; nj < 4; nj++)
                ldsm4(bf[2 * nj][0], bf[2 * nj][1], bf[2 * nj + 1][0], bf[2 * nj + 1][1],
                      bTh + (uint32_t)(nj * 16 * STRIDE) * 2u + ko);
#pragma unroll
            for (int mi = 0; mi < 4; mi++)
#pragma unroll
                for (int ni = 0; ni < 8; ni++)
                    mma16(acc[mi][ni], af[mi], bf[ni]);
        }
    }

    // Epilogue: c0/c1 at (row, 2*tig[+1]); c2/c3 at (row+8, ...)
#pragma unroll
    for (int mi = 0; mi < 4; mi++) {
        const int r0 = blockM + wm * 64 + mi * 16 + grp;
#pragma unroll
        for (int ni = 0; ni < 8; ni++) {
            const int c0 = blockN + wn * 64 + ni * 8 + 2 * tig;
            float2 v0 = make_float2(acc[mi][ni][0], acc[mi][ni][1]);
            float2 v1 = make_float2(acc[mi][ni][2], acc[mi][ni][3]);
            *reinterpret_cast<float2*>(C + (size_t)r0 * N_DIM + c0) = v0;
            *reinterpret_cast<float2*>(C + (size_t)(r0 + 8) * N_DIM + c0) = v1;
        }
    }
}

// ---------------------------------------------------------------------------
extern "C" void kernel_launch(void* const* d_in, const int* in_sizes, int n_in,
                              void* d_out, int out_size) {
    const float* x  = (const float*)d_in[0];  // [8192,2048]
    const float* w  = (const float*)d_in[1];  // [2048,8192]
    const float* la = (const float*)d_in[2];  // [2048,16]
    const float* lb = (const float*)d_in[3];  // [16,8192]
    float* out = (float*)d_out;               // [8192,8192]

    void *xh_p = nullptr, *wh_p = nullptr;
    cudaGetSymbolAddress(&xh_p, g_xh);
    cudaGetSymbolAddress(&wh_p, g_wh);

    prep_all<<<PX_BLOCKS + FW_BLOCKS_X * FW_BLOCKS_Y, 256>>>(
        (const float4*)x, (uint4*)xh_p, w, la, lb, (__half*)wh_p);

    cudaFuncSetAttribute(gemm_f16, cudaFuncAttributeMaxDynamicSharedMemorySize, SMEM_BYTES);
    gemm_f16<<<dim3(N_DIM / 128, M_DIM / 128), 128, SMEM_BYTES>>>(
        (const __half*)xh_p, (const __half*)wh_p, out);
}

// round 9
// speedup vs baseline: 1.0742x; 1.0285x over previous
#include <cuda_runtime.h>
#include <cuda_fp16.h>
#include <cstdint>
#include <cstddef>

// out[M,N] = x[M,K] @ (w[K,N] + 2 * lora_a[K,16] @ lora_b[16,N])
#define M_DIM 8192
#define N_DIM 8192
#define K_DIM 2048
#define SCALE 2.0f

// Scratch (device globals — allocation-free per harness rules).
// g_xh: x -> fp16 (rn), plain [M,K] row-major
// g_wh: fused W' = w + 2*A@B -> fp16, TRANSPOSED [N,K] (K-contiguous)
__device__ __align__(16) __half g_xh[(size_t)M_DIM * K_DIM];
__device__ __align__(16) __half g_wh[(size_t)N_DIM * K_DIM];

// ---------------------------------------------------------------------------
// Kernel 1: x -> fp16, straight layout. One thread: 8 floats -> 8 halves.
// ---------------------------------------------------------------------------
__global__ __launch_bounds__(256) void prep_x(const float4* __restrict__ x,
                                              uint4* __restrict__ xh) {
    const size_t i = (size_t)blockIdx.x * 256 + threadIdx.x;
    const float4 v0 = x[i * 2 + 0];
    const float4 v1 = x[i * 2 + 1];
    __half2 h[4];
    h[0] = __floats2half2_rn(v0.x, v0.y);
    h[1] = __floats2half2_rn(v0.z, v0.w);
    h[2] = __floats2half2_rn(v1.x, v1.y);
    h[3] = __floats2half2_rn(v1.z, v1.w);
    xh[i] = *reinterpret_cast<const uint4*>(h);
}

// ---------------------------------------------------------------------------
// Kernel 2: g_wh[n][k] = fp16(w[k][n] + 2*(A@B)[k][n]); 32x32 smem transpose
// ---------------------------------------------------------------------------
__global__ __launch_bounds__(256) void fuse_w_t(const float* __restrict__ w,
                                                const float* __restrict__ la,
                                                const float* __restrict__ lb) {
    __shared__ float t[32][33];
    __shared__ float bs[16][32];
    const int n0 = blockIdx.x * 32, k0 = blockIdx.y * 32;
    const int tid = threadIdx.x;
    const int tx = tid & 31, ty = tid >> 5;
    {
        int i0 = tid;
        bs[i0 >> 5][i0 & 31] = lb[(size_t)(i0 >> 5) * N_DIM + n0 + (i0 & 31)];
        int i1 = tid + 256;
        bs[i1 >> 5][i1 & 31] = lb[(size_t)(i1 >> 5) * N_DIM + n0 + (i1 & 31)];
    }
    __syncthreads();
#pragma unroll
    for (int i = 0; i < 4; i++) {
        const int kl = ty + 8 * i;
        const int k = k0 + kl;
        const float* ar = la + (size_t)k * 16;
        float acc = 0.f;
#pragma unroll
        for (int r = 0; r < 16; r++) acc += ar[r] * bs[r][tx];
        t[kl][tx] = w[(size_t)k * N_DIM + n0 + tx] + SCALE * acc;
    }
    __syncthreads();
#pragma unroll
    for (int i = 0; i < 4; i++) {
        const int nl = ty + 8 * i;
        g_wh[(size_t)(n0 + nl) * K_DIM + k0 + tx] = __float2half_rn(t[tx][nl]);
    }
}

// ---------------------------------------------------------------------------
// Kernel 3: fp16 mma.sync GEMM (f32 accum). CTA 128x128 / 256 threads,
// 8 warps of 64x32 (2M x 4N), 2 CTAs/SM -> 4 warps/SMSP. KTILE 64,
// 2-stage cp.async, ldmatrix.m8n8.x4 fragments.
// ---------------------------------------------------------------------------
constexpr int KTILE = 64;                   // halves per k-tile
constexpr int STRIDE = 72;                  // 64 + 8 pad (halves) = 144 B rows
constexpr int T_ST = 128 * STRIDE;          // 9216 halves (18 KB)
constexpr int STAGE = 2 * T_ST;             // A + B per stage (36 KB)
constexpr int SMEM_BYTES = 2 * STAGE * 2;   // 147456 B

__device__ __forceinline__ void ldsm4(uint32_t& r0, uint32_t& r1, uint32_t& r2,
                                      uint32_t& r3, uint32_t addr) {
    asm volatile("ldmatrix.sync.aligned.m8n8.x4.shared.b16 {%0,%1,%2,%3}, [%4];"
                 : "=r"(r0), "=r"(r1), "=r"(r2), "=r"(r3) : "r"(addr));
}
__device__ __forceinline__ void mma16(float c[4], const uint32_t a[4], const uint32_t b[2]) {
    asm volatile(
        "mma.sync.aligned.m16n8k16.row.col.f32.f16.f16.f32 "
        "{%0,%1,%2,%3}, {%4,%5,%6,%7}, {%8,%9}, {%0,%1,%2,%3};\n"
        : "+f"(c[0]), "+f"(c[1]), "+f"(c[2]), "+f"(c[3])
        : "r"(a[0]), "r"(a[1]), "r"(a[2]), "r"(a[3]), "r"(b[0]), "r"(b[1]));
}

__global__ __launch_bounds__(256, 2) void gemm_f16(const __half* __restrict__ A,
                                                   const __half* __restrict__ B,
                                                   float* __restrict__ C) {
    extern __shared__ __half smem[];
    const int tid = threadIdx.x;
    const int lane = tid & 31;
    const int warp = tid >> 5;   // 0..7
    const int wm = warp >> 2;    // 2 warps along M (64 rows)
    const int wn = warp & 3;     // 4 warps along N (32 cols)
    const int grp = lane >> 2;   // 0..7
    const int tig = lane & 3;    // 0..3
    const int blockM = blockIdx.y * 128;
    const int blockN = blockIdx.x * 128;

    const uint32_t smem_u = (uint32_t)__cvta_generic_to_shared(smem);

    float acc[4][4][4];
#pragma unroll
    for (int i = 0; i < 4; i++)
#pragma unroll
        for (int j = 0; j < 4; j++)
#pragma unroll
            for (int l = 0; l < 4; l++) acc[i][j][l] = 0.f;

    // cp.async: each tile = 128 rows x 8 chunks of 16B; 256 threads -> 4/thread
    auto load_stage = [&](int s, int k0) {
        const uint32_t baseA = smem_u + (uint32_t)(s * STAGE) * 2u;
        const uint32_t baseB = baseA + (uint32_t)T_ST * 2u;
#pragma unroll
        for (int i = 0; i < 4; i++) {
            const int idx = tid + i * 256;
            const int row = idx >> 3, ch = idx & 7;
            const __half* g = A + (size_t)(blockM + row) * K_DIM + k0 + ch * 8;
            const uint32_t d = baseA + (uint32_t)(row * STRIDE + ch * 8) * 2u;
            asm volatile("cp.async.cg.shared.global [%0], [%1], 16;\n" ::"r"(d), "l"(g));
        }
#pragma unroll
        for (int i = 0; i < 4; i++) {
            const int idx = tid + i * 256;
            const int row = idx >> 3, ch = idx & 7;
            const __half* g = B + (size_t)(blockN + row) * K_DIM + k0 + ch * 8;
            const uint32_t d = baseB + (uint32_t)(row * STRIDE + ch * 8) * 2u;
            asm volatile("cp.async.cg.shared.global [%0], [%1], 16;\n" ::"r"(d), "l"(g));
        }
    };

    load_stage(0, 0);
    asm volatile("cp.async.commit_group;\n" ::: "memory");

    // ldmatrix per-thread addresses:
    // A x4 (per mi): matrices = {rows+0..7, k0-7}, {rows+8, k0-7},
    //                {rows+0..7, k8-15}, {rows+8, k8-15}
    const int aRow = wm * 64 + (lane & 7) + 8 * ((lane >> 3) & 1);
    const int aKc = (lane >> 4) & 1;
    // B x4 (per nj): covers 16 n-rows: {n+0..7,k0-7},{n+0..7,k8-15},
    //                {n+8..15,k0-7},{n+8..15,k8-15}
    const int bRow = wn * 32 + (lane & 7) + 8 * ((lane >> 4) & 1);
    const int bKc = (lane >> 3) & 1;

    const int KTILES = K_DIM / KTILE;  // 32
    for (int kt = 0; kt < KTILES; kt++) {
        asm volatile("cp.async.wait_group 0;\n" ::: "memory");
        __syncthreads();
        if (kt + 1 < KTILES) load_stage((kt + 1) & 1, (kt + 1) * KTILE);
        asm volatile("cp.async.commit_group;\n" ::: "memory");

        const uint32_t stBase = smem_u + (uint32_t)((kt & 1) * STAGE) * 2u;
        const uint32_t aTh = stBase + (uint32_t)(aRow * STRIDE + aKc * 8) * 2u;
        const uint32_t bTh = stBase + (uint32_t)(T_ST + bRow * STRIDE + bKc * 8) * 2u;
#pragma unroll
        for (int ks = 0; ks < 4; ks++) {          // 4 x k16 per KTILE=64
            const uint32_t ko = (uint32_t)(ks * 16) * 2u;
            uint32_t af[4][4], bf[4][2];
#pragma unroll
            for (int mi = 0; mi < 4; mi++)
                ldsm4(af[mi][0], af[mi][1], af[mi][2], af[mi][3],
                      aTh + (uint32_t)(mi * 16 * STRIDE) * 2u + ko);
#pragma unroll
            for (int nj = 0; nj < 2; nj++)
                ldsm4(bf[2 * nj][0], bf[2 * nj][1], bf[2 * nj + 1][0], bf[2 * nj + 1][1],
                      bTh + (uint32_t)(nj * 16 * STRIDE) * 2u + ko);
#pragma unroll
            for (int mi = 0; mi < 4; mi++)
#pragma unroll
                for (int ni = 0; ni < 4; ni++)
                    mma16(acc[mi][ni], af[mi], bf[ni]);
        }
    }

    // Epilogue: c0/c1 at (row, 2*tig[+1]); c2/c3 at (row+8, ...)
#pragma unroll
    for (int mi = 0; mi < 4; mi++) {
        const int r0 = blockM + wm * 64 + mi * 16 + grp;
#pragma unroll
        for (int ni = 0; ni < 4; ni++) {
            const int c0 = blockN + wn * 32 + ni * 8 + 2 * tig;
            float2 v0 = make_float2(acc[mi][ni][0], acc[mi][ni][1]);
            float2 v1 = make_float2(acc[mi][ni][2], acc[mi][ni][3]);
            *reinterpret_cast<float2*>(C + (size_t)r0 * N_DIM + c0) = v0;
            *reinterpret_cast<float2*>(C + (size_t)(r0 + 8) * N_DIM + c0) = v1;
        }
    }
}

// ---------------------------------------------------------------------------
extern "C" void kernel_launch(void* const* d_in, const int* in_sizes, int n_in,
                              void* d_out, int out_size) {
    const float* x  = (const float*)d_in[0];  // [8192,2048]
    const float* w  = (const float*)d_in[1];  // [2048,8192]
    const float* la = (const float*)d_in[2];  // [2048,16]
    const float* lb = (const float*)d_in[3];  // [16,8192]
    float* out = (float*)d_out;               // [8192,8192]

    void *xh_p = nullptr, *wh_p = nullptr;
    cudaGetSymbolAddress(&xh_p, g_xh);
    cudaGetSymbolAddress(&wh_p, g_wh);

    prep_x<<<(int)(((size_t)M_DIM * K_DIM / 8) / 256), 256>>>(
        (const float4*)x, (uint4*)xh_p);
    fuse_w_t<<<dim3(N_DIM / 32, K_DIM / 32), 256>>>(w, la, lb);

    cudaFuncSetAttribute(gemm_f16, cudaFuncAttributeMaxDynamicSharedMemorySize, SMEM_BYTES);
    gemm_f16<<<dim3(N_DIM / 128, M_DIM / 128), 256, SMEM_BYTES>>>(
        (const __half*)xh_p, (const __half*)wh_p, out);
}

// round 11
// speedup vs baseline: 1.1060x; 1.0296x over previous
#include <cuda_runtime.h>
#include <cuda_fp16.h>
#include <cstdint>
#include <cstddef>

// out[M,N] = x[M,K] @ (w[K,N] + 2 * lora_a[K,16] @ lora_b[16,N])
#define M_DIM 8192
#define N_DIM 8192
#define K_DIM 2048
#define SCALE 2.0f

// Scratch (device globals — allocation-free per harness rules).
// g_xh: x -> fp16 (rn), plain [M,K] row-major
// g_wh: fused W' = w + 2*A@B -> fp16, TRANSPOSED [N,K] (K-contiguous)
__device__ __align__(16) __half g_xh[(size_t)M_DIM * K_DIM];
__device__ __align__(16) __half g_wh[(size_t)N_DIM * K_DIM];

// ---------------------------------------------------------------------------
// Kernel 1: x -> fp16, straight layout. One thread: 8 floats -> 8 halves.
// ---------------------------------------------------------------------------
__global__ __launch_bounds__(256) void prep_x(const float4* __restrict__ x,
                                              uint4* __restrict__ xh) {
    const size_t i = (size_t)blockIdx.x * 256 + threadIdx.x;
    const float4 v0 = x[i * 2 + 0];
    const float4 v1 = x[i * 2 + 1];
    __half2 h[4];
    h[0] = __floats2half2_rn(v0.x, v0.y);
    h[1] = __floats2half2_rn(v0.z, v0.w);
    h[2] = __floats2half2_rn(v1.x, v1.y);
    h[3] = __floats2half2_rn(v1.z, v1.w);
    xh[i] = *reinterpret_cast<const uint4*>(h);
}

// ---------------------------------------------------------------------------
// Kernel 2: g_wh[n][k] = fp16(w[k][n] + 2*(A@B)[k][n]); 32x32 smem transpose
// ---------------------------------------------------------------------------
__global__ __launch_bounds__(256) void fuse_w_t(const float* __restrict__ w,
                                                const float* __restrict__ la,
                                                const float* __restrict__ lb) {
    __shared__ float t[32][33];
    __shared__ float bs[16][32];
    const int n0 = blockIdx.x * 32, k0 = blockIdx.y * 32;
    const int tid = threadIdx.x;
    const int tx = tid & 31, ty = tid >> 5;
    {
        int i0 = tid;
        bs[i0 >> 5][i0 & 31] = lb[(size_t)(i0 >> 5) * N_DIM + n0 + (i0 & 31)];
        int i1 = tid + 256;
        bs[i1 >> 5][i1 & 31] = lb[(size_t)(i1 >> 5) * N_DIM + n0 + (i1 & 31)];
    }
    __syncthreads();
#pragma unroll
    for (int i = 0; i < 4; i++) {
        const int kl = ty + 8 * i;
        const int k = k0 + kl;
        const float* ar = la + (size_t)k * 16;
        float acc = 0.f;
#pragma unroll
        for (int r = 0; r < 16; r++) acc += ar[r] * bs[r][tx];
        t[kl][tx] = w[(size_t)k * N_DIM + n0 + tx] + SCALE * acc;
    }
    __syncthreads();
#pragma unroll
    for (int i = 0; i < 4; i++) {
        const int nl = ty + 8 * i;
        g_wh[(size_t)(n0 + nl) * K_DIM + k0 + tx] = __float2half_rn(t[tx][nl]);
    }
}

// ---------------------------------------------------------------------------
// Kernel 3: fp16 mma.sync GEMM (f32 accum). CTA 128x128 / 128 threads,
// 4 warps of 64x64, 2 CTAs/SM. KTILE=32, FOUR stages, wait_group 2 ->
// the per-kt barrier never waits on memory. ldmatrix fragments.
// ---------------------------------------------------------------------------
constexpr int KTILE = 32;                   // halves per k-tile
constexpr int STRIDE = 40;                  // 32 + 8 pad halves = 80 B rows
                                            // (16B-multiple for cp.async; LDSM
                                            // banks 20r mod 32 all distinct)
constexpr int T_ST = 128 * STRIDE;          // 5120 halves (10 KB)
constexpr int STAGE = 2 * T_ST;             // A + B per stage (20 KB)
constexpr int STAGES = 4;
constexpr int SMEM_BYTES = STAGES * STAGE * 2;  // 81920 B

__device__ __forceinline__ void ldsm4(uint32_t& r0, uint32_t& r1, uint32_t& r2,
                                      uint32_t& r3, uint32_t addr) {
    asm volatile("ldmatrix.sync.aligned.m8n8.x4.shared.b16 {%0,%1,%2,%3}, [%4];"
                 : "=r"(r0), "=r"(r1), "=r"(r2), "=r"(r3) : "r"(addr));
}
__device__ __forceinline__ void mma16(float c[4], const uint32_t a[4], const uint32_t b[2]) {
    asm volatile(
        "mma.sync.aligned.m16n8k16.row.col.f32.f16.f16.f32 "
        "{%0,%1,%2,%3}, {%4,%5,%6,%7}, {%8,%9}, {%0,%1,%2,%3};\n"
        : "+f"(c[0]), "+f"(c[1]), "+f"(c[2]), "+f"(c[3])
        : "r"(a[0]), "r"(a[1]), "r"(a[2]), "r"(a[3]), "r"(b[0]), "r"(b[1]));
}

__global__ __launch_bounds__(128, 2) void gemm_f16(const __half* __restrict__ A,
                                                   const __half* __restrict__ B,
                                                   float* __restrict__ C) {
    extern __shared__ __half smem[];
    const int tid = threadIdx.x;
    const int lane = tid & 31;
    const int warp = tid >> 5;   // 0..3
    const int wm = warp >> 1;    // 2 warps along M (64 rows)
    const int wn = warp & 1;     // 2 warps along N (64 cols)
    const int grp = lane >> 2;   // 0..7
    const int tig = lane & 3;    // 0..3
    const int blockM = blockIdx.y * 128;
    const int blockN = blockIdx.x * 128;

    const uint32_t smem_u = (uint32_t)__cvta_generic_to_shared(smem);

    float acc[4][8][4];
#pragma unroll
    for (int i = 0; i < 4; i++)
#pragma unroll
        for (int j = 0; j < 8; j++)
#pragma unroll
            for (int l = 0; l < 4; l++) acc[i][j][l] = 0.f;

    // One stage: A,B tiles of 128 rows x 4 chunks (16B); 512 chunks each,
    // 128 threads -> 4 chunks/thread per tile.
    auto load_stage = [&](int s, int k0) {
        const uint32_t baseA = smem_u + (uint32_t)(s * STAGE) * 2u;
        const uint32_t baseB = baseA + (uint32_t)T_ST * 2u;
#pragma unroll
        for (int i = 0; i < 4; i++) {
            const int idx = tid + i * 128;
            const int row = idx >> 2, ch = idx & 3;
            const __half* g = A + (size_t)(blockM + row) * K_DIM + k0 + ch * 8;
            const uint32_t d = baseA + (uint32_t)(row * STRIDE + ch * 8) * 2u;
            asm volatile("cp.async.cg.shared.global [%0], [%1], 16;\n" ::"r"(d), "l"(g));
        }
#pragma unroll
        for (int i = 0; i < 4; i++) {
            const int idx = tid + i * 128;
            const int row = idx >> 2, ch = idx & 3;
            const __half* g = B + (size_t)(blockN + row) * K_DIM + k0 + ch * 8;
            const uint32_t d = baseB + (uint32_t)(row * STRIDE + ch * 8) * 2u;
            asm volatile("cp.async.cg.shared.global [%0], [%1], 16;\n" ::"r"(d), "l"(g));
        }
    };

    // Prologue: stages 0,1,2 = groups 0,1,2
#pragma unroll
    for (int p = 0; p < 3; p++) {
        load_stage(p, p * KTILE);
        asm volatile("cp.async.commit_group;\n" ::: "memory");
    }

    // ldmatrix per-thread addresses (same mapping as validated round 8):
    const int aRow = wm * 64 + (lane & 7) + 8 * ((lane >> 3) & 1);
    const int aKc = (lane >> 4) & 1;
    const int bRow = wn * 64 + (lane & 7) + 8 * ((lane >> 4) & 1);
    const int bKc = (lane >> 3) & 1;

    const int KTILES = K_DIM / KTILE;  // 64
    int st = 0;
    for (int kt = 0; kt < KTILES; kt++) {
        // group kt (stage st) guaranteed complete; newer 2 may be in flight
        asm volatile("cp.async.wait_group 2;\n" ::: "memory");
        __syncthreads();

        // prefetch kt+3 into stage (st+3)&3, consumed at kt-1 (safe: all
        // warps passed the kt barrier => finished kt-1 compute)
        if (kt + 3 < KTILES) load_stage((st + 3) & 3, (kt + 3) * KTILE);
        asm volatile("cp.async.commit_group;\n" ::: "memory");  // one group per kt

        const uint32_t stBase = smem_u + (uint32_t)(st * STAGE) * 2u;
        const uint32_t aTh = stBase + (uint32_t)(aRow * STRIDE + aKc * 8) * 2u;
        const uint32_t bTh = stBase + (uint32_t)(T_ST + bRow * STRIDE + bKc * 8) * 2u;
#pragma unroll
        for (int ks = 0; ks < 2; ks++) {          // 2 x k16 per KTILE=32
            const uint32_t ko = (uint32_t)(ks * 16) * 2u;
            uint32_t af[4][4], bf[8][2];
#pragma unroll
            for (int mi = 0; mi < 4; mi++)
                ldsm4(af[mi][0], af[mi][1], af[mi][2], af[mi][3],
                      aTh + (uint32_t)(mi * 16 * STRIDE) * 2u + ko);
#pragma unroll
            for (int nj = 0; nj < 4; nj++)
                ldsm4(bf[2 * nj][0], bf[2 * nj][1], bf[2 * nj + 1][0], bf[2 * nj + 1][1],
                      bTh + (uint32_t)(nj * 16 * STRIDE) * 2u + ko);
#pragma unroll
            for (int mi = 0; mi < 4; mi++)
#pragma unroll
                for (int ni = 0; ni < 8; ni++)
                    mma16(acc[mi][ni], af[mi], bf[ni]);
        }
        st = (st + 1) & 3;
    }

    // Epilogue: c0/c1 at (row, 2*tig[+1]); c2/c3 at (row+8, ...)
#pragma unroll
    for (int mi = 0; mi < 4; mi++) {
        const int r0 = blockM + wm * 64 + mi * 16 + grp;
#pragma unroll
        for (int ni = 0; ni < 8; ni++) {
            const int c0 = blockN + wn * 64 + ni * 8 + 2 * tig;
            float2 v0 = make_float2(acc[mi][ni][0], acc[mi][ni][1]);
            float2 v1 = make_float2(acc[mi][ni][2], acc[mi][ni][3]);
            *reinterpret_cast<float2*>(C + (size_t)r0 * N_DIM + c0) = v0;
            *reinterpret_cast<float2*>(C + (size_t)(r0 + 8) * N_DIM + c0) = v1;
        }
    }
}

// ---------------------------------------------------------------------------
extern "C" void kernel_launch(void* const* d_in, const int* in_sizes, int n_in,
                              void* d_out, int out_size) {
    const float* x  = (const float*)d_in[0];  // [8192,2048]
    const float* w  = (const float*)d_in[1];  // [2048,8192]
    const float* la = (const float*)d_in[2];  // [2048,16]
    const float* lb = (const float*)d_in[3];  // [16,8192]
    float* out = (float*)d_out;               // [8192,8192]

    void *xh_p = nullptr, *wh_p = nullptr;
    cudaGetSymbolAddress(&xh_p, g_xh);
    cudaGetSymbolAddress(&wh_p, g_wh);

    prep_x<<<(int)(((size_t)M_DIM * K_DIM / 8) / 256), 256>>>(
        (const float4*)x, (uint4*)xh_p);
    fuse_w_t<<<dim3(N_DIM / 32, K_DIM / 32), 256>>>(w, la, lb);

    cudaFuncSetAttribute(gemm_f16, cudaFuncAttributeMaxDynamicSharedMemorySize, SMEM_BYTES);
    gemm_f16<<<dim3(N_DIM / 128, M_DIM / 128), 128, SMEM_BYTES>>>(
        (const __half*)xh_p, (const __half*)wh_p, out);
}

// round 12
// speedup vs baseline: 1.1506x; 1.0404x over previous
#include <cuda_runtime.h>
#include <cuda_fp16.h>
#include <cstdint>
#include <cstddef>

// out[M,N] = x[M,K] @ (w[K,N] + 2 * lora_a[K,16] @ lora_b[16,N])
#define M_DIM 8192
#define N_DIM 8192
#define K_DIM 2048
#define SCALE 2.0f

// Scratch (device globals — allocation-free per harness rules).
__device__ __align__(16) __half g_xh[(size_t)M_DIM * K_DIM];  // x -> fp16 [M,K]
__device__ __align__(16) __half g_wh[(size_t)N_DIM * K_DIM];  // W'^T fp16 [N,K]

// ---------------------------------------------------------------------------
// Kernel 1: x -> fp16, straight layout. One thread: 8 floats -> 8 halves.
// ---------------------------------------------------------------------------
__global__ __launch_bounds__(256) void prep_x(const float4* __restrict__ x,
                                              uint4* __restrict__ xh) {
    const size_t i = (size_t)blockIdx.x * 256 + threadIdx.x;
    const float4 v0 = x[i * 2 + 0];
    const float4 v1 = x[i * 2 + 1];
    __half2 h[4];
    h[0] = __floats2half2_rn(v0.x, v0.y);
    h[1] = __floats2half2_rn(v0.z, v0.w);
    h[2] = __floats2half2_rn(v1.x, v1.y);
    h[3] = __floats2half2_rn(v1.z, v1.w);
    xh[i] = *reinterpret_cast<const uint4*>(h);
}

// ---------------------------------------------------------------------------
// Kernel 2: g_wh[n][k] = fp16(w[k][n] + 2*(A@B)[k][n]); 32x32 smem transpose
// ---------------------------------------------------------------------------
__global__ __launch_bounds__(256) void fuse_w_t(const float* __restrict__ w,
                                                const float* __restrict__ la,
                                                const float* __restrict__ lb) {
    __shared__ float t[32][33];
    __shared__ float bs[16][32];
    const int n0 = blockIdx.x * 32, k0 = blockIdx.y * 32;
    const int tid = threadIdx.x;
    const int tx = tid & 31, ty = tid >> 5;
    {
        int i0 = tid;
        bs[i0 >> 5][i0 & 31] = lb[(size_t)(i0 >> 5) * N_DIM + n0 + (i0 & 31)];
        int i1 = tid + 256;
        bs[i1 >> 5][i1 & 31] = lb[(size_t)(i1 >> 5) * N_DIM + n0 + (i1 & 31)];
    }
    __syncthreads();
#pragma unroll
    for (int i = 0; i < 4; i++) {
        const int kl = ty + 8 * i;
        const int k = k0 + kl;
        const float* ar = la + (size_t)k * 16;
        float acc = 0.f;
#pragma unroll
        for (int r = 0; r < 16; r++) acc += ar[r] * bs[r][tx];
        t[kl][tx] = w[(size_t)k * N_DIM + n0 + tx] + SCALE * acc;
    }
    __syncthreads();
#pragma unroll
    for (int i = 0; i < 4; i++) {
        const int nl = ty + 8 * i;
        g_wh[(size_t)(n0 + nl) * K_DIM + k0 + tx] = __float2half_rn(t[tx][nl]);
    }
}

// ---------------------------------------------------------------------------
// Kernel 3: PERSISTENT fp16 mma.sync GEMM (f32 accum). 304 CTAs (2/SM),
// each loops over ~13.5 tiles of 128x128. 4-stage cp.async pipeline stays
// full ACROSS tile boundaries (global step counter g; stage = g & 3;
// wait_group 2 => step-g data ready). ldmatrix fragments, 64x64 warp tiles.
// ---------------------------------------------------------------------------
constexpr int KTILE = 32;                   // halves per k-tile
constexpr int STRIDE = 40;                  // 80 B rows (16B-multiple; LDSM banks
                                            // 20r mod 32 all distinct)
constexpr int T_ST = 128 * STRIDE;          // 5120 halves (10 KB)
constexpr int STAGE = 2 * T_ST;             // A + B per stage (20 KB)
constexpr int SMEM_BYTES = 4 * STAGE * 2;   // 81920 B
constexpr int KTILES = K_DIM / KTILE;       // 64 steps per tile
constexpr int NT = (M_DIM / 128) * (N_DIM / 128);  // 4096 tiles
constexpr int GRID = 304;                   // 152 SMs x 2 CTAs

__device__ __forceinline__ void ldsm4(uint32_t& r0, uint32_t& r1, uint32_t& r2,
                                      uint32_t& r3, uint32_t addr) {
    asm volatile("ldmatrix.sync.aligned.m8n8.x4.shared.b16 {%0,%1,%2,%3}, [%4];"
                 : "=r"(r0), "=r"(r1), "=r"(r2), "=r"(r3) : "r"(addr));
}
__device__ __forceinline__ void mma16(float c[4], const uint32_t a[4], const uint32_t b[2]) {
    asm volatile(
        "mma.sync.aligned.m16n8k16.row.col.f32.f16.f16.f32 "
        "{%0,%1,%2,%3}, {%4,%5,%6,%7}, {%8,%9}, {%0,%1,%2,%3};\n"
        : "+f"(c[0]), "+f"(c[1]), "+f"(c[2]), "+f"(c[3])
        : "r"(a[0]), "r"(a[1]), "r"(a[2]), "r"(a[3]), "r"(b[0]), "r"(b[1]));
}

__global__ __launch_bounds__(128, 2) void gemm_f16(const __half* __restrict__ A,
                                                   const __half* __restrict__ B,
                                                   float* __restrict__ C) {
    extern __shared__ __half smem[];
    const int tid = threadIdx.x;
    const int lane = tid & 31;
    const int warp = tid >> 5;   // 0..3
    const int wm = warp >> 1;    // 2 warps along M (64 rows)
    const int wn = warp & 1;     // 2 warps along N (64 cols)
    const int grp = lane >> 2;   // 0..7
    const int tig = lane & 3;    // 0..3
    const int cta = blockIdx.x;

    const uint32_t smem_u = (uint32_t)__cvta_generic_to_shared(smem);

    // this CTA's work: tiles cta, cta+GRID, ...  (s-th tile)
    const int nt = (NT - cta + GRID - 1) / GRID;
    const int total_g = nt * KTILES;

    float acc[4][8][4];
#pragma unroll
    for (int i = 0; i < 4; i++)
#pragma unroll
        for (int j = 0; j < 8; j++)
#pragma unroll
            for (int l = 0; l < 4; l++) acc[i][j][l] = 0.f;

    // Load pipeline step l: tile ordinal l/64, k-chunk l%64, stage l&3.
    auto load_stage = [&](int l) {
        const int tl = cta + (l >> 6) * GRID;      // global tile index
        const int bM = (tl >> 6) * 128;
        const int bN = (tl & 63) * 128;
        const int k0 = (l & 63) * KTILE;
        const uint32_t baseA = smem_u + (uint32_t)((l & 3) * STAGE) * 2u;
        const uint32_t baseB = baseA + (uint32_t)T_ST * 2u;
#pragma unroll
        for (int i = 0; i < 4; i++) {
            const int idx = tid + i * 128;
            const int row = idx >> 2, ch = idx & 3;
            const __half* g = A + (size_t)(bM + row) * K_DIM + k0 + ch * 8;
            const uint32_t d = baseA + (uint32_t)(row * STRIDE + ch * 8) * 2u;
            asm volatile("cp.async.cg.shared.global [%0], [%1], 16;\n" ::"r"(d), "l"(g));
        }
#pragma unroll
        for (int i = 0; i < 4; i++) {
            const int idx = tid + i * 128;
            const int row = idx >> 2, ch = idx & 3;
            const __half* g = B + (size_t)(bN + row) * K_DIM + k0 + ch * 8;
            const uint32_t d = baseB + (uint32_t)(row * STRIDE + ch * 8) * 2u;
            asm volatile("cp.async.cg.shared.global [%0], [%1], 16;\n" ::"r"(d), "l"(g));
        }
    };

    // Prologue: steps 0,1,2 -> stages 0,1,2 (every CTA has >= 13 tiles)
#pragma unroll
    for (int p = 0; p < 3; p++) {
        load_stage(p);
        asm volatile("cp.async.commit_group;\n" ::: "memory");
    }

    // ldmatrix per-thread addresses (mapping validated in round 8):
    const int aRow = wm * 64 + (lane & 7) + 8 * ((lane >> 3) & 1);
    const int aKc = (lane >> 4) & 1;
    const int bRow = wn * 64 + (lane & 7) + 8 * ((lane >> 4) & 1);
    const int bKc = (lane >> 3) & 1;

    for (int g = 0; g < total_g; g++) {
        // group g complete (committed 3 steps ago); newest 2 may be in flight
        asm volatile("cp.async.wait_group 2;\n" ::: "memory");
        __syncthreads();

        const int l = g + 3;     // prefetch into stage consumed at step g-1
        if (l < total_g) load_stage(l);
        asm volatile("cp.async.commit_group;\n" ::: "memory");  // 1 group / step

        const uint32_t stBase = smem_u + (uint32_t)((g & 3) * STAGE) * 2u;
        const uint32_t aTh = stBase + (uint32_t)(aRow * STRIDE + aKc * 8) * 2u;
        const uint32_t bTh = stBase + (uint32_t)(T_ST + bRow * STRIDE + bKc * 8) * 2u;
#pragma unroll
        for (int ks = 0; ks < 2; ks++) {          // 2 x k16 per KTILE=32
            const uint32_t ko = (uint32_t)(ks * 16) * 2u;
            uint32_t af[4][4], bf[8][2];
#pragma unroll
            for (int mi = 0; mi < 4; mi++)
                ldsm4(af[mi][0], af[mi][1], af[mi][2], af[mi][3],
                      aTh + (uint32_t)(mi * 16 * STRIDE) * 2u + ko);
#pragma unroll
            for (int nj = 0; nj < 4; nj++)
                ldsm4(bf[2 * nj][0], bf[2 * nj][1], bf[2 * nj + 1][0], bf[2 * nj + 1][1],
                      bTh + (uint32_t)(nj * 16 * STRIDE) * 2u + ko);
#pragma unroll
            for (int mi = 0; mi < 4; mi++)
#pragma unroll
                for (int ni = 0; ni < 8; ni++)
                    mma16(acc[mi][ni], af[mi], bf[ni]);
        }

        // Tile finished: drain accumulators (overlaps next tile's in-flight
        // loads), then reset. No smem hazard -> no extra barrier needed.
        if ((g & (KTILES - 1)) == KTILES - 1) {
            const int tl = cta + (g >> 6) * GRID;
            const int bM = (tl >> 6) * 128;
            const int bN = (tl & 63) * 128;
#pragma unroll
            for (int mi = 0; mi < 4; mi++) {
                const int r0 = bM + wm * 64 + mi * 16 + grp;
#pragma unroll
                for (int ni = 0; ni < 8; ni++) {
                    const int c0 = bN + wn * 64 + ni * 8 + 2 * tig;
                    float2 v0 = make_float2(acc[mi][ni][0], acc[mi][ni][1]);
                    float2 v1 = make_float2(acc[mi][ni][2], acc[mi][ni][3]);
                    *reinterpret_cast<float2*>(C + (size_t)r0 * N_DIM + c0) = v0;
                    *reinterpret_cast<float2*>(C + (size_t)(r0 + 8) * N_DIM + c0) = v1;
#pragma unroll
                    for (int q = 0; q < 4; q++) acc[mi][ni][q] = 0.f;
                }
            }
        }
    }
}

// ---------------------------------------------------------------------------
extern "C" void kernel_launch(void* const* d_in, const int* in_sizes, int n_in,
                              void* d_out, int out_size) {
    const float* x  = (const float*)d_in[0];  // [8192,2048]
    const float* w  = (const float*)d_in[1];  // [2048,8192]
    const float* la = (const float*)d_in[2];  // [2048,16]
    const float* lb = (const float*)d_in[3];  // [16,8192]
    float* out = (float*)d_out;               // [8192,8192]

    void *xh_p = nullptr, *wh_p = nullptr;
    cudaGetSymbolAddress(&xh_p, g_xh);
    cudaGetSymbolAddress(&wh_p, g_wh);

    prep_x<<<(int)(((size_t)M_DIM * K_DIM / 8) / 256), 256>>>(
        (const float4*)x, (uint4*)xh_p);
    fuse_w_t<<<dim3(N_DIM / 32, K_DIM / 32), 256>>>(w, la, lb);

    cudaFuncSetAttribute(gemm_f16, cudaFuncAttributeMaxDynamicSharedMemorySize, SMEM_BYTES);
    gemm_f16<<<GRID, 128, SMEM_BYTES>>>(
        (const __half*)xh_p, (const __half*)wh_p, out);
}